// round 15
// baseline (speedup 1.0000x reference)
#include <cuda_runtime.h>

#define DD 96
#define HH 192
#define WW 192
#define W4N (WW/4)                // 48
#define NFULL (DD*HH*WW)          // 3538944
#define NQ    (NFULL/4)
#define NL1 (48*96*96)            // 442368
#define NL2 (24*48*48)            // 55296
#define NL3 (12*24*24)            // 6912

#define DT   0.01f
#define RE   0.001f
#define INVD (-1.0f/6.0f)         // 1/diag, diag = -6

// ---------------- scratch (device globals, float4-aligned) ----------------
__device__ float4 g_U4[NQ], g_V4[NQ], g_W4[NQ];
__device__ float4 g_BU4[NQ], g_BV4[NQ], g_BW4[NQ];
__device__ float4 g_R04[NQ], g_R0b4[NQ], g_P4[NQ];
__device__ float g_R1[NL1], g_R3[NL3];
__device__ float g_W2[NL2], g_W1[NL1];

// ---------------- helpers ----------------
__device__ __forceinline__ float g(const float4 v, int k) {
    switch (k) { case 0: return v.x; case 1: return v.y; case 2: return v.z; default: return v.w; }
}
__device__ __forceinline__ void setk(float4& v, int k, float val) {
    switch (k) { case 0: v.x = val; break; case 1: v.y = val; break;
                 case 2: v.z = val; break; default: v.w = val; }
}

// 1/(1+DT*s) to 1e-8 rel err for DT*s in [0, 0.01): (1-x)(1+x^2); 3 FMA, no MUFU
__device__ __forceinline__ float invof(float s) {
    float x = DT * s;
    return (1.0f - x) * fmaf(x, x, 1.0f);
}
__device__ __forceinline__ float4 invof4(float4 s) {
    return make_float4(invof(s.x), invof(s.y), invof(s.z), invof(s.w));
}

struct St { float4 c, ym, yp, zm, zp; float xm, xp; };

__device__ __forceinline__ St gather(const float* __restrict__ f, int z, int y, int x4) {
    St s;
    const float4* f4 = (const float4*)f;
    s.c  = f4[(z*HH + y)*W4N + x4];
    s.ym = (y > 0)    ? f4[(z*HH + y-1)*W4N + x4]   : make_float4(0,0,0,0);
    s.yp = (y < HH-1) ? f4[(z*HH + y+1)*W4N + x4]   : make_float4(0,0,0,0);
    s.zm = (z > 0)    ? f4[((z-1)*HH + y)*W4N + x4] : make_float4(0,0,0,0);
    s.zp = (z < DD-1) ? f4[((z+1)*HH + y)*W4N + x4] : make_float4(0,0,0,0);
    int base = (z*HH + y)*WW + 4*x4;
    s.xm = (x4 > 0)     ? f[base - 1] : 0.0f;
    s.xp = (x4 < W4N-1) ? f[base + 4] : 0.0f;
    return s;
}

// elementwise invof over a whole stencil (computed ONCE, reused for u,v,w)
__device__ __forceinline__ St inv_st(const St& s) {
    St r;
    r.c  = invof4(s.c);
    r.ym = invof4(s.ym); r.yp = invof4(s.yp);
    r.zm = invof4(s.zm); r.zp = invof4(s.zp);
    r.xm = invof(s.xm);  r.xp = invof(s.xp);
    return r;
}

// pure multiplies
__device__ __forceinline__ void damp(St& a, const St& s) {
    a.c.x*=s.c.x;   a.c.y*=s.c.y;   a.c.z*=s.c.z;   a.c.w*=s.c.w;
    a.ym.x*=s.ym.x; a.ym.y*=s.ym.y; a.ym.z*=s.ym.z; a.ym.w*=s.ym.w;
    a.yp.x*=s.yp.x; a.yp.y*=s.yp.y; a.yp.z*=s.yp.z; a.yp.w*=s.yp.w;
    a.zm.x*=s.zm.x; a.zm.y*=s.zm.y; a.zm.z*=s.zm.z; a.zm.w*=s.zm.w;
    a.zp.x*=s.zp.x; a.zp.y*=s.zp.y; a.zp.z*=s.zp.z; a.zp.w*=s.zp.w;
    a.xm*=s.xm;     a.xp*=s.xp;
}

#define NBRS(sf, k, fc, fxm, fxp, fym, fyp, fzm, fzp)                       \
    float fc  = g((sf).c, k);                                               \
    float fxm = (k)     ? g((sf).c, (k)-1) : (sf).xm;                       \
    float fxp = ((k)<3) ? g((sf).c, (k)+1) : (sf).xp;                       \
    float fym = g((sf).ym, k), fyp = g((sf).yp, k);                         \
    float fzm = g((sf).zm, k), fzp = g((sf).zp, k);

// W1 prolongation fetch (zero outside domain)
__device__ __forceinline__ float wmat(const float* __restrict__ w1, int z, int y, int x) {
    if ((unsigned)z >= (unsigned)DD || (unsigned)y >= (unsigned)HH || (unsigned)x >= (unsigned)WW)
        return 0.0f;
    return w1[((z>>1)*(HH/2) + (y>>1))*(WW/2) + (x>>1)];
}

// ---------------- predictor: BU/BV/BW ----------------
__global__ __launch_bounds__(192) void k_pred(const float* __restrict__ vu,
                                              const float* __restrict__ vv,
                                              const float* __restrict__ vw,
                                              const float* __restrict__ vp,
                                              const float* __restrict__ sg) {
    int x4 = threadIdx.x, y = blockIdx.x*4 + threadIdx.y, z = blockIdx.y;

    St ss = gather(sg, z, y, x4);
    St si = inv_st(ss);
    St su = gather(vu, z, y, x4); damp(su, si);
    St sv = gather(vv, z, y, x4); damp(sv, si);
    St sw = gather(vw, z, y, x4); damp(sw, si);
    St sp = gather(vp, z, y, x4);

    float4 bu4, bv4, bw4;
#pragma unroll
    for (int k = 0; k < 4; k++) {
        int x = 4*x4 + k;
        int nout = (x==0)+(x==WW-1)+(y==0)+(y==HH-1)+(z==0)+(z==DD-1);
        float hn = 0.5f * (float)nout;
        float invc = g(si.c, k);

        NBRS(su, k, uc, uxm, uxp, uym, uyp, uzm, uzp);
        NBRS(sv, k, vc, vxm, vxp, vym, vyp, vzm, vzp);
        NBRS(sw, k, wc, wxm, wxp, wym, wyp, wzm, wzp);
        NBRS(sp, k, pc, pxm, pxp, pym, pyp, pzm, pzp);
        (void)pc;

        float dxp = 0.5f*(pxp-pxm), dyp = 0.5f*(pyp-pym), dzp = 0.5f*(pzp-pzm);

        float ku = (uxm+uxp+uym+uyp+uzm+uzp - 6.0f*uc) + hn*uc;
        float kv = (vxm+vxp+vym+vyp+vzm+vzp - 6.0f*vc) + hn*vc;
        float kw = (wxm+wxp+wym+wyp+wzm+wzp - 6.0f*wc) + hn*wc;

        float dxu = 0.5f*(uxp-uxm), dyu = 0.5f*(uyp-uym), dzu = 0.5f*(uzp-uzm);
        float dxv = 0.5f*(vxp-vxm), dyv = 0.5f*(vyp-vym), dzv = 0.5f*(vzp-vzm);
        float dxw = 0.5f*(wxp-wxm), dyw = 0.5f*(wyp-wym), dzw = 0.5f*(wzp-wzm);

        setk(bu4, k, (uc + 0.5f*(RE*ku*DT - uc*dxu*DT - vc*dyu*DT - wc*dzu*DT) - dxp*DT) * invc);
        setk(bv4, k, (vc + 0.5f*(RE*kv*DT - uc*dxv*DT - vc*dyv*DT - wc*dzv*DT) - dyp*DT) * invc);
        setk(bw4, k, (wc + 0.5f*(RE*kw*DT - uc*dxw*DT - vc*dyw*DT - wc*dzw*DT) - dzp*DT) * invc);
    }
    int i4 = (z*HH + y)*W4N + x4;
    g_BU4[i4] = bu4; g_BV4[i4] = bv4; g_BW4[i4] = bw4;
}

// ---------------- corrector: write U,V,W ----------------
__global__ __launch_bounds__(192) void k_stage3(const float* __restrict__ vu,
                                                const float* __restrict__ vv,
                                                const float* __restrict__ vw,
                                                const float* __restrict__ vp,
                                                const float* __restrict__ sg) {
    const float* BU = (const float*)g_BU4;
    const float* BV = (const float*)g_BV4;
    const float* BW = (const float*)g_BW4;
    int x4 = threadIdx.x, y = blockIdx.x*4 + threadIdx.y, z = blockIdx.y;
    int i4 = (z*HH + y)*W4N + x4;

    St sbu = gather(BU, z, y, x4);
    St sbv = gather(BV, z, y, x4);
    St sbw = gather(BW, z, y, x4);
    St sp  = gather(vp, z, y, x4);

    float4 inv4 = invof4(((const float4*)sg)[i4]);
    float4 u0 = ((const float4*)vu)[i4];
    float4 v0 = ((const float4*)vv)[i4];
    float4 w0 = ((const float4*)vw)[i4];

    float4 un4, vn4, wn4;
#pragma unroll
    for (int k = 0; k < 4; k++) {
        int x = 4*x4 + k;
        int nout = (x==0)+(x==WW-1)+(y==0)+(y==HH-1)+(z==0)+(z==DD-1);
        float hn = 0.5f * (float)nout;
        float invc = g(inv4, k);
        float uc = g(u0,k)*invc, vc = g(v0,k)*invc, wc = g(w0,k)*invc;

        NBRS(sbu, k, buc, buxm, buxp, buym, buyp, buzm, buzp);
        NBRS(sbv, k, bvc, bvxm, bvxp, bvym, bvyp, bvzm, bvzp);
        NBRS(sbw, k, bwc, bwxm, bwxp, bwym, bwyp, bwzm, bwzp);
        NBRS(sp,  k, pc,  pxm,  pxp,  pym,  pyp,  pzm,  pzp);
        (void)pc;

        float dxp = 0.5f*(pxp-pxm), dyp = 0.5f*(pyp-pym), dzp = 0.5f*(pzp-pzm);

        float kub = (buxm+buxp+buym+buyp+buzm+buzp - 6.0f*buc) + hn*buc;
        float kvb = (bvxm+bvxp+bvym+bvyp+bvzm+bvzp - 6.0f*bvc) + hn*bvc;
        float kwb = (bwxm+bwxp+bwym+bwyp+bwzm+bwzp - 6.0f*bwc) + hn*bwc;

        float dx_bu=0.5f*(buxp-buxm), dy_bu=0.5f*(buyp-buym), dz_bu=0.5f*(buzp-buzm);
        float dx_bv=0.5f*(bvxp-bvxm), dy_bv=0.5f*(bvyp-bvym), dz_bv=0.5f*(bvzp-bvzm);
        float dx_bw=0.5f*(bwxp-bwxm), dy_bw=0.5f*(bwyp-bwym), dz_bw=0.5f*(bwzp-bwzm);

        setk(un4, k, (uc + RE*kub*DT - buc*dx_bu*DT - bvc*dy_bu*DT - bwc*dz_bu*DT - dxp*DT) * invc);
        setk(vn4, k, (vc + RE*kvb*DT - buc*dx_bv*DT - bvc*dy_bv*DT - bwc*dz_bv*DT - dyp*DT) * invc);
        setk(wn4, k, (wc + RE*kwb*DT - buc*dx_bw*DT - bvc*dy_bw*DT - bwc*dz_bw*DT - dzp*DT) * invc);
    }
    g_U4[i4] = un4; g_V4[i4] = vn4; g_W4[i4] = wn4;
}

// shared tail: reduce 2x4x192 plane-pair of r values into 192 R1 cells
// sm layout: sm[zi][ty][x4] as float4 (fine x = 4*x4+k)
__device__ __forceinline__ void r1_tail(float4 (&sm)[2][4][48], int by, int bz) {
    __syncthreads();
    int tid = threadIdx.y*48 + threadIdx.x;   // 0..191
    int cx = tid % 96, cy = tid / 96;         // cy 0..1
    const float* s0 = (const float*)&sm[0][2*cy][0];
    const float* s1 = (const float*)&sm[0][2*cy+1][0];
    const float* s2 = (const float*)&sm[1][2*cy][0];
    const float* s3 = (const float*)&sm[1][2*cy+1][0];
    float sum = s0[2*cx] + s0[2*cx+1] + s1[2*cx] + s1[2*cx+1]
              + s2[2*cx] + s2[2*cx+1] + s3[2*cx] + s3[2*cx+1];
    // R1 dims (48,96,96): z1 = bz, y1 = by*2 + cy
    g_R1[(bz*96 + by*2 + cy)*96 + cx] = 0.125f * sum;
}

// ------- fine residual (iter 1) + fused R0->R1 restriction -------
__global__ __launch_bounds__(192) void k_residb(const float* __restrict__ vp) {
    __shared__ float4 sm[2][4][48];
    const float* U = (const float*)g_U4;
    const float* V = (const float*)g_V4;
    const float* W = (const float*)g_W4;
    int x4 = threadIdx.x, ty = threadIdx.y;
    int y = blockIdx.x*4 + ty;
    int z0 = blockIdx.y*2;

#pragma unroll
    for (int zi = 0; zi < 2; zi++) {
        int z = z0 + zi;
        int i4 = (z*HH + y)*W4N + x4;

        float4 ucv = ((const float4*)U)[i4];
        int base = (z*HH + y)*WW + 4*x4;
        float uxm_s = (x4 > 0)     ? U[base - 1] : 0.0f;
        float uxp_s = (x4 < W4N-1) ? U[base + 4] : 0.0f;

        const float4* V4 = (const float4*)V;
        float4 vym = (y > 0)    ? V4[(z*HH + y-1)*W4N + x4] : make_float4(0,0,0,0);
        float4 vyp = (y < HH-1) ? V4[(z*HH + y+1)*W4N + x4] : make_float4(0,0,0,0);

        const float4* Wp4 = (const float4*)W;
        float4 wzm = (z > 0)    ? Wp4[((z-1)*HH + y)*W4N + x4] : make_float4(0,0,0,0);
        float4 wzp = (z < DD-1) ? Wp4[((z+1)*HH + y)*W4N + x4] : make_float4(0,0,0,0);

        St sp = gather(vp, z, y, x4);

        float4 r4;
#pragma unroll
        for (int k = 0; k < 4; k++) {
            float uxm = k ? g(ucv,k-1) : uxm_s;
            float uxp = (k<3) ? g(ucv,k+1) : uxp_s;
            float dxu = 0.5f*(uxp - uxm);
            float dyv = 0.5f*(g(vyp,k) - g(vym,k));
            float dzw = 0.5f*(g(wzp,k) - g(wzm,k));
            float b = -(dxu + dyv + dzw) * (1.0f/DT);

            NBRS(sp, k, pc, pxm, pxp, pym, pyp, pzm, pzp);
            float lap = pxm+pxp+pym+pyp+pzm+pzp - 6.0f*pc;
            setk(r4, k, lap - b);
        }
        g_R04[i4] = r4;
        sm[zi][ty][x4] = r4;
    }
    r1_tail(sm, blockIdx.x, blockIdx.y);
}

// ------- fused double restriction: R1(48x96x96) -> R3(12x24x24) directly -------
__global__ __launch_bounds__(256) void k_restrict13(float* __restrict__ mirror) {
    int i = blockIdx.x*blockDim.x + threadIdx.x;
    if (i >= NL3) return;
    int x3 = i % 24, t = i / 24, y3 = t % 24, z3 = t / 24;
    float r3 = 0.0f;
#pragma unroll
    for (int dz = 0; dz < 2; dz++)
#pragma unroll
        for (int dy = 0; dy < 2; dy++)
#pragma unroll
            for (int dx = 0; dx < 2; dx++) {
                int z1 = (2*z3+dz)*2, y1 = (2*y3+dy)*2, x1 = (2*x3+dx)*2;
                const float* b = g_R1 + (z1*96 + y1)*96 + x1;
                float2 a0 = *(const float2*)(b);
                float2 a1 = *(const float2*)(b + 96);
                float2 a2 = *(const float2*)(b + 96*96);
                float2 a3 = *(const float2*)(b + 96*96 + 96);
                r3 += 0.125f*(a0.x+a0.y + a1.x+a1.y + a2.x+a2.y + a3.x+a3.y);
            }
    r3 *= 0.125f;
    g_R3[i] = r3;
    if (mirror) mirror[i] = r3;
}

// ---- L2 smooth with inline r2 = avg8(R1) ----
__global__ __launch_bounds__(256) void k_smooth2() {
    int i = blockIdx.x*blockDim.x + threadIdx.x;
    if (i >= NL2) return;
    int x = i % 48, t = i / 48, y = t % 48, z = t / 48;
    auto wp = [&](int zz, int yy, int xx) -> float {
        if ((unsigned)zz >= 24u || (unsigned)yy >= 48u || (unsigned)xx >= 48u)
            return 0.0f;
        return INVD * g_R3[((zz>>1)*24 + (yy>>1))*24 + (xx>>1)];
    };
    float c = wp(z,y,x);
    float a = wp(z,y,x-1)+wp(z,y,x+1)+wp(z,y-1,x)+wp(z,y+1,x)+wp(z-1,y,x)+wp(z+1,y,x) - 6.0f*c;

    const float* b = g_R1 + ((2*z)*96 + 2*y)*96 + 2*x;
    float2 a0 = *(const float2*)(b);
    float2 a1 = *(const float2*)(b + 96);
    float2 a2 = *(const float2*)(b + 96*96);
    float2 a3 = *(const float2*)(b + 96*96 + 96);
    float r2 = 0.125f*(a0.x+a0.y + a1.x+a1.y + a2.x+a2.y + a3.x+a3.y);

    g_W2[i] = c - a*INVD + r2*INVD;
}

// ---- L1 smooth ----
__global__ __launch_bounds__(256) void k_smooth1() {
    int i = blockIdx.x*blockDim.x + threadIdx.x;
    if (i >= NL1) return;
    int x = i % 96, t = i / 96, y = t % 96, z = t / 96;
    auto wp = [&](int zz, int yy, int xx) -> float {
        if ((unsigned)zz >= 48u || (unsigned)yy >= 96u || (unsigned)xx >= 96u)
            return 0.0f;
        return g_W2[((zz>>1)*48 + (yy>>1))*48 + (xx>>1)];
    };
    float c = wp(z,y,x);
    float a = wp(z,y,x-1)+wp(z,y,x+1)+wp(z,y-1,x)+wp(z,y+1,x)+wp(z-1,y,x)+wp(z+1,y,x) - 6.0f*c;
    g_W1[i] = c - a*INVD + g_R1[i]*INVD;
}

// -------- fused iter-1 p-update + iter-2 residual + R0b->R1 restriction --------
// d = -prol(w1) - r0/diag ; P = p + d ; R0b = lap(d) + r0
__global__ __launch_bounds__(192) void k_pup_resid(const float* __restrict__ vp) {
    __shared__ float4 sm[2][4][48];
    const float* R0 = (const float*)g_R04;
    int x4 = threadIdx.x, ty = threadIdx.y;
    int y = blockIdx.x*4 + ty;
    int z0 = blockIdx.y*2;

#pragma unroll
    for (int zi = 0; zi < 2; zi++) {
        int z = z0 + zi;
        int i4 = (z*HH + y)*W4N + x4;

        St sr = gather(R0, z, y, x4);
        float4 pc4 = ((const float4*)vp)[i4];

        float4 p4, rr4;
#pragma unroll
        for (int k = 0; k < 4; k++) {
            int x = 4*x4 + k;
            NBRS(sr, k, rc, rxm, rxp, rym, ryp, rzm, rzp);

            float dc  = -wmat(g_W1, z, y, x)   - rc  * INVD;
            float dxm = -wmat(g_W1, z, y, x-1) - rxm * INVD;
            float dxp = -wmat(g_W1, z, y, x+1) - rxp * INVD;
            float dym = -wmat(g_W1, z, y-1, x) - rym * INVD;
            float dyp = -wmat(g_W1, z, y+1, x) - ryp * INVD;
            float dzm = -wmat(g_W1, z-1, y, x) - rzm * INVD;
            float dzp = -wmat(g_W1, z+1, y, x) - rzp * INVD;

            float lapd = dxm + dxp + dym + dyp + dzm + dzp - 6.0f*dc;
            setk(p4, k, g(pc4, k) + dc);
            setk(rr4, k, lapd + rc);
        }
        g_P4[i4] = p4;
        g_R0b4[i4] = rr4;
        sm[zi][ty][x4] = rr4;
    }
    r1_tail(sm, blockIdx.x, blockIdx.y);
}

// -------- fused iter-2 p-update + final projection + sb --------
__global__ __launch_bounds__(192) void k_pfinal(const float* __restrict__ sg,
                                                float* __restrict__ out_p, float* __restrict__ out_wmg,
                                                float* __restrict__ ou, float* __restrict__ ov,
                                                float* __restrict__ ow) {
    const float* P  = (const float*)g_P4;
    const float* R0 = (const float*)g_R0b4;
    int x4 = threadIdx.x, y = blockIdx.x*4 + threadIdx.y, z = blockIdx.y;
    int i4 = (z*HH + y)*W4N + x4;

    St sp = gather(P, z, y, x4);
    St sr = gather(R0, z, y, x4);
    float4 u4 = g_U4[i4], v4 = g_V4[i4], w4 = g_W4[i4];
    float4 inv4 = invof4(((const float4*)sg)[i4]);

    float4 op4, owm4, ou4, ov4, ow4;
#pragma unroll
    for (int k = 0; k < 4; k++) {
        int x = 4*x4 + k;
        NBRS(sp, k, pc, pxm, pxp, pym, pyp, pzm, pzp);
        NBRS(sr, k, rc, rxm, rxp, rym, ryp, rzm, rzp);

        float wm   = wmat(g_W1, z, y, x);
        float p2c  = pc  - wm                    - rc  * INVD;
        float p2xm = pxm - wmat(g_W1, z, y, x-1) - rxm * INVD;
        float p2xp = pxp - wmat(g_W1, z, y, x+1) - rxp * INVD;
        float p2ym = pym - wmat(g_W1, z, y-1, x) - rym * INVD;
        float p2yp = pyp - wmat(g_W1, z, y+1, x) - ryp * INVD;
        float p2zm = pzm - wmat(g_W1, z-1, y, x) - rzm * INVD;
        float p2zp = pzp - wmat(g_W1, z+1, y, x) - rzp * INVD;

        float dxp = 0.5f*(p2xp - p2xm);
        float dyp = 0.5f*(p2yp - p2ym);
        float dzp = 0.5f*(p2zp - p2zm);

        float invc = g(inv4, k);
        setk(op4, k, p2c);
        setk(owm4, k, wm);
        setk(ou4, k, (g(u4,k) - dxp*DT) * invc);
        setk(ov4, k, (g(v4,k) - dyp*DT) * invc);
        setk(ow4, k, (g(w4,k) - dzp*DT) * invc);
    }
    ((float4*)out_p)[i4]   = op4;
    ((float4*)out_wmg)[i4] = owm4;
    ((float4*)ou)[i4] = ou4;
    ((float4*)ov)[i4] = ov4;
    ((float4*)ow)[i4] = ow4;
}

// ---------------- launch ----------------
extern "C" void kernel_launch(void* const* d_in, const int* in_sizes, int n_in,
                              void* d_out, int out_size) {
    const float* vu = (const float*)d_in[0];
    const float* vv = (const float*)d_in[1];
    const float* vw = (const float*)d_in[2];
    const float* vp = (const float*)d_in[3];
    const float* sg = (const float*)d_in[4];

    float* out     = (float*)d_out;
    float* out_u   = out;
    float* out_v   = out + (size_t)NFULL;
    float* out_w   = out + (size_t)2*NFULL;
    float* out_p   = out + (size_t)3*NFULL;
    float* out_wmg = out + (size_t)4*NFULL;
    float* out_r   = out + (size_t)5*NFULL;

    dim3 blk(W4N, 4, 1);          // 192 threads
    dim3 grd(HH/4, DD);           // 4608 blocks
    dim3 grd2(HH/4, DD/2);        // 2304 blocks (fused R1 producers)

    k_pred  <<<grd, blk>>>(vu, vv, vw, vp, sg);
    k_stage3<<<grd, blk>>>(vu, vv, vw, vp, sg);

    // ---- MG iteration 1 (p = vp): residual + R1 fused ----
    k_residb<<<grd2, blk>>>(vp);
    k_restrict13<<<(NL3+255)/256, 256>>>(nullptr);
    k_smooth2<<<(NL2+255)/256, 256>>>();
    k_smooth1<<<(NL1+255)/256, 256>>>();

    // ---- fused: P = p1; R0b = lap(d) + r0; R1 = restrict(R0b) ----
    k_pup_resid<<<grd2, blk>>>(vp);

    // ---- MG iteration 2 coarse solve ----
    k_restrict13<<<(NL3+255)/256, 256>>>(out_r);
    k_smooth2<<<(NL2+255)/256, 256>>>();
    k_smooth1<<<(NL1+255)/256, 256>>>();

    k_pfinal<<<grd, blk>>>(sg, out_p, out_wmg, out_u, out_v, out_w);
}

// round 16
// speedup vs baseline: 1.0254x; 1.0254x over previous
#include <cuda_runtime.h>

#define DD 96
#define HH 192
#define WW 192
#define W4N (WW/4)                // 48
#define NFULL (DD*HH*WW)          // 3538944
#define NQ    (NFULL/4)
#define NL1 (48*96*96)            // 442368
#define NL2 (24*48*48)            // 55296
#define NL3 (12*24*24)            // 6912

#define DT   0.01f
#define RE   0.001f
#define INVD (-1.0f/6.0f)         // 1/diag, diag = -6

// ---------------- scratch (device globals, float4-aligned) ----------------
__device__ float4 g_U4[NQ], g_V4[NQ], g_W4[NQ];
__device__ float4 g_BU4[NQ], g_BV4[NQ], g_BW4[NQ];
__device__ float4 g_R04[NQ], g_R0b4[NQ], g_P4[NQ];
__device__ float g_R1[NL1], g_R3[NL3];
__device__ float g_W2[NL2], g_W1[NL1];

// ---------------- helpers ----------------
__device__ __forceinline__ float g(const float4 v, int k) {
    switch (k) { case 0: return v.x; case 1: return v.y; case 2: return v.z; default: return v.w; }
}
__device__ __forceinline__ void setk(float4& v, int k, float val) {
    switch (k) { case 0: v.x = val; break; case 1: v.y = val; break;
                 case 2: v.z = val; break; default: v.w = val; }
}

// 1/(1+DT*s) to 1e-8 rel err for DT*s in [0, 0.01): (1-x)(1+x^2); 3 FMA, no MUFU
__device__ __forceinline__ float invof(float s) {
    float x = DT * s;
    return (1.0f - x) * fmaf(x, x, 1.0f);
}
__device__ __forceinline__ float4 invof4(float4 s) {
    return make_float4(invof(s.x), invof(s.y), invof(s.z), invof(s.w));
}

struct St { float4 c, ym, yp, zm, zp; float xm, xp; };

__device__ __forceinline__ St gather(const float* __restrict__ f, int z, int y, int x4) {
    St s;
    const float4* f4 = (const float4*)f;
    s.c  = f4[(z*HH + y)*W4N + x4];
    s.ym = (y > 0)    ? f4[(z*HH + y-1)*W4N + x4]   : make_float4(0,0,0,0);
    s.yp = (y < HH-1) ? f4[(z*HH + y+1)*W4N + x4]   : make_float4(0,0,0,0);
    s.zm = (z > 0)    ? f4[((z-1)*HH + y)*W4N + x4] : make_float4(0,0,0,0);
    s.zp = (z < DD-1) ? f4[((z+1)*HH + y)*W4N + x4] : make_float4(0,0,0,0);
    int base = (z*HH + y)*WW + 4*x4;
    s.xm = (x4 > 0)     ? f[base - 1] : 0.0f;
    s.xp = (x4 < W4N-1) ? f[base + 4] : 0.0f;
    return s;
}

// elementwise invof over a whole stencil (computed ONCE, reused for u,v,w)
__device__ __forceinline__ St inv_st(const St& s) {
    St r;
    r.c  = invof4(s.c);
    r.ym = invof4(s.ym); r.yp = invof4(s.yp);
    r.zm = invof4(s.zm); r.zp = invof4(s.zp);
    r.xm = invof(s.xm);  r.xp = invof(s.xp);
    return r;
}

// pure multiplies
__device__ __forceinline__ void damp(St& a, const St& s) {
    a.c.x*=s.c.x;   a.c.y*=s.c.y;   a.c.z*=s.c.z;   a.c.w*=s.c.w;
    a.ym.x*=s.ym.x; a.ym.y*=s.ym.y; a.ym.z*=s.ym.z; a.ym.w*=s.ym.w;
    a.yp.x*=s.yp.x; a.yp.y*=s.yp.y; a.yp.z*=s.yp.z; a.yp.w*=s.yp.w;
    a.zm.x*=s.zm.x; a.zm.y*=s.zm.y; a.zm.z*=s.zm.z; a.zm.w*=s.zm.w;
    a.zp.x*=s.zp.x; a.zp.y*=s.zp.y; a.zp.z*=s.zp.z; a.zp.w*=s.zp.w;
    a.xm*=s.xm;     a.xp*=s.xp;
}

#define NBRS(sf, k, fc, fxm, fxp, fym, fyp, fzm, fzp)                       \
    float fc  = g((sf).c, k);                                               \
    float fxm = (k)     ? g((sf).c, (k)-1) : (sf).xm;                       \
    float fxp = ((k)<3) ? g((sf).c, (k)+1) : (sf).xp;                       \
    float fym = g((sf).ym, k), fyp = g((sf).yp, k);                         \
    float fzm = g((sf).zm, k), fzp = g((sf).zp, k);

// W1 prolongation fetch (zero outside domain)
__device__ __forceinline__ float wmat(const float* __restrict__ w1, int z, int y, int x) {
    if ((unsigned)z >= (unsigned)DD || (unsigned)y >= (unsigned)HH || (unsigned)x >= (unsigned)WW)
        return 0.0f;
    return w1[((z>>1)*(HH/2) + (y>>1))*(WW/2) + (x>>1)];
}

// ---------------- predictor: BU/BV/BW ----------------
__global__ __launch_bounds__(192) void k_pred(const float* __restrict__ vu,
                                              const float* __restrict__ vv,
                                              const float* __restrict__ vw,
                                              const float* __restrict__ vp,
                                              const float* __restrict__ sg) {
    int x4 = threadIdx.x, y = blockIdx.x*4 + threadIdx.y, z = blockIdx.y;

    St ss = gather(sg, z, y, x4);
    St si = inv_st(ss);
    St su = gather(vu, z, y, x4); damp(su, si);
    St sv = gather(vv, z, y, x4); damp(sv, si);
    St sw = gather(vw, z, y, x4); damp(sw, si);
    St sp = gather(vp, z, y, x4);

    float4 bu4, bv4, bw4;
#pragma unroll
    for (int k = 0; k < 4; k++) {
        int x = 4*x4 + k;
        int nout = (x==0)+(x==WW-1)+(y==0)+(y==HH-1)+(z==0)+(z==DD-1);
        float hn = 0.5f * (float)nout;
        float invc = g(si.c, k);

        NBRS(su, k, uc, uxm, uxp, uym, uyp, uzm, uzp);
        NBRS(sv, k, vc, vxm, vxp, vym, vyp, vzm, vzp);
        NBRS(sw, k, wc, wxm, wxp, wym, wyp, wzm, wzp);
        NBRS(sp, k, pc, pxm, pxp, pym, pyp, pzm, pzp);
        (void)pc;

        float dxp = 0.5f*(pxp-pxm), dyp = 0.5f*(pyp-pym), dzp = 0.5f*(pzp-pzm);

        float ku = (uxm+uxp+uym+uyp+uzm+uzp - 6.0f*uc) + hn*uc;
        float kv = (vxm+vxp+vym+vyp+vzm+vzp - 6.0f*vc) + hn*vc;
        float kw = (wxm+wxp+wym+wyp+wzm+wzp - 6.0f*wc) + hn*wc;

        float dxu = 0.5f*(uxp-uxm), dyu = 0.5f*(uyp-uym), dzu = 0.5f*(uzp-uzm);
        float dxv = 0.5f*(vxp-vxm), dyv = 0.5f*(vyp-vym), dzv = 0.5f*(vzp-vzm);
        float dxw = 0.5f*(wxp-wxm), dyw = 0.5f*(wyp-wym), dzw = 0.5f*(wzp-wzm);

        setk(bu4, k, (uc + 0.5f*(RE*ku*DT - uc*dxu*DT - vc*dyu*DT - wc*dzu*DT) - dxp*DT) * invc);
        setk(bv4, k, (vc + 0.5f*(RE*kv*DT - uc*dxv*DT - vc*dyv*DT - wc*dzv*DT) - dyp*DT) * invc);
        setk(bw4, k, (wc + 0.5f*(RE*kw*DT - uc*dxw*DT - vc*dyw*DT - wc*dzw*DT) - dzp*DT) * invc);
    }
    int i4 = (z*HH + y)*W4N + x4;
    g_BU4[i4] = bu4; g_BV4[i4] = bv4; g_BW4[i4] = bw4;
}

// ---------------- corrector: write U,V,W ----------------
__global__ __launch_bounds__(192) void k_stage3(const float* __restrict__ vu,
                                                const float* __restrict__ vv,
                                                const float* __restrict__ vw,
                                                const float* __restrict__ vp,
                                                const float* __restrict__ sg) {
    const float* BU = (const float*)g_BU4;
    const float* BV = (const float*)g_BV4;
    const float* BW = (const float*)g_BW4;
    int x4 = threadIdx.x, y = blockIdx.x*4 + threadIdx.y, z = blockIdx.y;
    int i4 = (z*HH + y)*W4N + x4;

    St sbu = gather(BU, z, y, x4);
    St sbv = gather(BV, z, y, x4);
    St sbw = gather(BW, z, y, x4);
    St sp  = gather(vp, z, y, x4);

    float4 inv4 = invof4(((const float4*)sg)[i4]);
    float4 u0 = ((const float4*)vu)[i4];
    float4 v0 = ((const float4*)vv)[i4];
    float4 w0 = ((const float4*)vw)[i4];

    float4 un4, vn4, wn4;
#pragma unroll
    for (int k = 0; k < 4; k++) {
        int x = 4*x4 + k;
        int nout = (x==0)+(x==WW-1)+(y==0)+(y==HH-1)+(z==0)+(z==DD-1);
        float hn = 0.5f * (float)nout;
        float invc = g(inv4, k);
        float uc = g(u0,k)*invc, vc = g(v0,k)*invc, wc = g(w0,k)*invc;

        NBRS(sbu, k, buc, buxm, buxp, buym, buyp, buzm, buzp);
        NBRS(sbv, k, bvc, bvxm, bvxp, bvym, bvyp, bvzm, bvzp);
        NBRS(sbw, k, bwc, bwxm, bwxp, bwym, bwyp, bwzm, bwzp);
        NBRS(sp,  k, pc,  pxm,  pxp,  pym,  pyp,  pzm,  pzp);
        (void)pc;

        float dxp = 0.5f*(pxp-pxm), dyp = 0.5f*(pyp-pym), dzp = 0.5f*(pzp-pzm);

        float kub = (buxm+buxp+buym+buyp+buzm+buzp - 6.0f*buc) + hn*buc;
        float kvb = (bvxm+bvxp+bvym+bvyp+bvzm+bvzp - 6.0f*bvc) + hn*bvc;
        float kwb = (bwxm+bwxp+bwym+bwyp+bwzm+bwzp - 6.0f*bwc) + hn*bwc;

        float dx_bu=0.5f*(buxp-buxm), dy_bu=0.5f*(buyp-buym), dz_bu=0.5f*(buzp-buzm);
        float dx_bv=0.5f*(bvxp-bvxm), dy_bv=0.5f*(bvyp-bvym), dz_bv=0.5f*(bvzp-bvzm);
        float dx_bw=0.5f*(bwxp-bwxm), dy_bw=0.5f*(bwyp-bwym), dz_bw=0.5f*(bwzp-bwzm);

        setk(un4, k, (uc + RE*kub*DT - buc*dx_bu*DT - bvc*dy_bu*DT - bwc*dz_bu*DT - dxp*DT) * invc);
        setk(vn4, k, (vc + RE*kvb*DT - buc*dx_bv*DT - bvc*dy_bv*DT - bwc*dz_bv*DT - dyp*DT) * invc);
        setk(wn4, k, (wc + RE*kwb*DT - buc*dx_bw*DT - bvc*dy_bw*DT - bwc*dz_bw*DT - dzp*DT) * invc);
    }
    g_U4[i4] = un4; g_V4[i4] = vn4; g_W4[i4] = wn4;
}

// shared tail: reduce 2x4x192 plane-pair of r values into 192 R1 cells
__device__ __forceinline__ void r1_tail(float4 (&sm)[2][4][48], int by, int bz) {
    __syncthreads();
    int tid = threadIdx.y*48 + threadIdx.x;   // 0..191
    int cx = tid % 96, cy = tid / 96;         // cy 0..1
    const float* s0 = (const float*)&sm[0][2*cy][0];
    const float* s1 = (const float*)&sm[0][2*cy+1][0];
    const float* s2 = (const float*)&sm[1][2*cy][0];
    const float* s3 = (const float*)&sm[1][2*cy+1][0];
    float sum = s0[2*cx] + s0[2*cx+1] + s1[2*cx] + s1[2*cx+1]
              + s2[2*cx] + s2[2*cx+1] + s3[2*cx] + s3[2*cx+1];
    g_R1[(bz*96 + by*2 + cy)*96 + cx] = 0.125f * sum;
}

// ------- fine residual (iter 1) + fused R0->R1 restriction -------
__global__ __launch_bounds__(192) void k_residb(const float* __restrict__ vp) {
    __shared__ float4 sm[2][4][48];
    const float* U = (const float*)g_U4;
    const float* V = (const float*)g_V4;
    const float* W = (const float*)g_W4;
    int x4 = threadIdx.x, ty = threadIdx.y;
    int y = blockIdx.x*4 + ty;
    int z0 = blockIdx.y*2;

#pragma unroll
    for (int zi = 0; zi < 2; zi++) {
        int z = z0 + zi;
        int i4 = (z*HH + y)*W4N + x4;

        float4 ucv = ((const float4*)U)[i4];
        int base = (z*HH + y)*WW + 4*x4;
        float uxm_s = (x4 > 0)     ? U[base - 1] : 0.0f;
        float uxp_s = (x4 < W4N-1) ? U[base + 4] : 0.0f;

        const float4* V4 = (const float4*)V;
        float4 vym = (y > 0)    ? V4[(z*HH + y-1)*W4N + x4] : make_float4(0,0,0,0);
        float4 vyp = (y < HH-1) ? V4[(z*HH + y+1)*W4N + x4] : make_float4(0,0,0,0);

        const float4* Wp4 = (const float4*)W;
        float4 wzm = (z > 0)    ? Wp4[((z-1)*HH + y)*W4N + x4] : make_float4(0,0,0,0);
        float4 wzp = (z < DD-1) ? Wp4[((z+1)*HH + y)*W4N + x4] : make_float4(0,0,0,0);

        St sp = gather(vp, z, y, x4);

        float4 r4;
#pragma unroll
        for (int k = 0; k < 4; k++) {
            float uxm = k ? g(ucv,k-1) : uxm_s;
            float uxp = (k<3) ? g(ucv,k+1) : uxp_s;
            float dxu = 0.5f*(uxp - uxm);
            float dyv = 0.5f*(g(vyp,k) - g(vym,k));
            float dzw = 0.5f*(g(wzp,k) - g(wzm,k));
            float b = -(dxu + dyv + dzw) * (1.0f/DT);

            NBRS(sp, k, pc, pxm, pxp, pym, pyp, pzm, pzp);
            float lap = pxm+pxp+pym+pyp+pzm+pzp - 6.0f*pc;
            setk(r4, k, lap - b);
        }
        g_R04[i4] = r4;
        sm[zi][ty][x4] = r4;
    }
    r1_tail(sm, blockIdx.x, blockIdx.y);
}

// ------- warp-per-cell double restriction: R1(48x96x96) -> R3(12x24x24) -------
// lane loads float2 (2 of the 64 R1 elements), shuffle-reduce, r3 = sum/64
__global__ __launch_bounds__(256) void k_restrict13(float* __restrict__ mirror) {
    int gw = (blockIdx.x*256 + threadIdx.x) >> 5;   // warp id = R3 cell, 0..6911
    int lane = threadIdx.x & 31;
    if (gw >= NL3) return;
    int x3 = gw % 24, t = gw / 24, y3 = t % 24, z3 = t / 24;

    int r = lane >> 1;                  // 0..15: (dz = r>>2, dy = r&3)
    int z1 = 4*z3 + (r >> 2);
    int y1 = 4*y3 + (r & 3);
    int x1 = 4*x3 + 2*(lane & 1);
    float2 a = *(const float2*)(g_R1 + (z1*96 + y1)*96 + x1);
    float s = a.x + a.y;
#pragma unroll
    for (int off = 16; off; off >>= 1)
        s += __shfl_down_sync(0xffffffffu, s, off);
    if (lane == 0) {
        float r3 = s * (1.0f/64.0f);
        g_R3[gw] = r3;
        if (mirror) mirror[gw] = r3;
    }
}

// ---- L2 smooth with inline r2 = avg8(R1) ----
__global__ __launch_bounds__(256) void k_smooth2() {
    int i = blockIdx.x*blockDim.x + threadIdx.x;
    if (i >= NL2) return;
    int x = i % 48, t = i / 48, y = t % 48, z = t / 48;
    auto wp = [&](int zz, int yy, int xx) -> float {
        if ((unsigned)zz >= 24u || (unsigned)yy >= 48u || (unsigned)xx >= 48u)
            return 0.0f;
        return INVD * g_R3[((zz>>1)*24 + (yy>>1))*24 + (xx>>1)];
    };
    float c = wp(z,y,x);
    float a = wp(z,y,x-1)+wp(z,y,x+1)+wp(z,y-1,x)+wp(z,y+1,x)+wp(z-1,y,x)+wp(z+1,y,x) - 6.0f*c;

    const float* b = g_R1 + ((2*z)*96 + 2*y)*96 + 2*x;
    float2 a0 = *(const float2*)(b);
    float2 a1 = *(const float2*)(b + 96);
    float2 a2 = *(const float2*)(b + 96*96);
    float2 a3 = *(const float2*)(b + 96*96 + 96);
    float r2 = 0.125f*(a0.x+a0.y + a1.x+a1.y + a2.x+a2.y + a3.x+a3.y);

    g_W2[i] = c - a*INVD + r2*INVD;
}

// ---- L1 smooth ----
__global__ __launch_bounds__(256) void k_smooth1() {
    int i = blockIdx.x*blockDim.x + threadIdx.x;
    if (i >= NL1) return;
    int x = i % 96, t = i / 96, y = t % 96, z = t / 96;
    auto wp = [&](int zz, int yy, int xx) -> float {
        if ((unsigned)zz >= 48u || (unsigned)yy >= 96u || (unsigned)xx >= 96u)
            return 0.0f;
        return g_W2[((zz>>1)*48 + (yy>>1))*48 + (xx>>1)];
    };
    float c = wp(z,y,x);
    float a = wp(z,y,x-1)+wp(z,y,x+1)+wp(z,y-1,x)+wp(z,y+1,x)+wp(z-1,y,x)+wp(z+1,y,x) - 6.0f*c;
    g_W1[i] = c - a*INVD + g_R1[i]*INVD;
}

// -------- fused iter-1 p-update + iter-2 residual + R0b->R1 restriction --------
__global__ __launch_bounds__(192) void k_pup_resid(const float* __restrict__ vp) {
    __shared__ float4 sm[2][4][48];
    const float* R0 = (const float*)g_R04;
    int x4 = threadIdx.x, ty = threadIdx.y;
    int y = blockIdx.x*4 + ty;
    int z0 = blockIdx.y*2;

#pragma unroll
    for (int zi = 0; zi < 2; zi++) {
        int z = z0 + zi;
        int i4 = (z*HH + y)*W4N + x4;

        St sr = gather(R0, z, y, x4);
        float4 pc4 = ((const float4*)vp)[i4];

        float4 p4, rr4;
#pragma unroll
        for (int k = 0; k < 4; k++) {
            int x = 4*x4 + k;
            NBRS(sr, k, rc, rxm, rxp, rym, ryp, rzm, rzp);

            float dc  = -wmat(g_W1, z, y, x)   - rc  * INVD;
            float dxm = -wmat(g_W1, z, y, x-1) - rxm * INVD;
            float dxp = -wmat(g_W1, z, y, x+1) - rxp * INVD;
            float dym = -wmat(g_W1, z, y-1, x) - rym * INVD;
            float dyp = -wmat(g_W1, z, y+1, x) - ryp * INVD;
            float dzm = -wmat(g_W1, z-1, y, x) - rzm * INVD;
            float dzp = -wmat(g_W1, z+1, y, x) - rzp * INVD;

            float lapd = dxm + dxp + dym + dyp + dzm + dzp - 6.0f*dc;
            setk(p4, k, g(pc4, k) + dc);
            setk(rr4, k, lapd + rc);
        }
        g_P4[i4] = p4;
        g_R0b4[i4] = rr4;
        sm[zi][ty][x4] = rr4;
    }
    r1_tail(sm, blockIdx.x, blockIdx.y);
}

// -------- fused iter-2 p-update + final projection + sb --------
__global__ __launch_bounds__(192) void k_pfinal(const float* __restrict__ sg,
                                                float* __restrict__ out_p, float* __restrict__ out_wmg,
                                                float* __restrict__ ou, float* __restrict__ ov,
                                                float* __restrict__ ow) {
    const float* P  = (const float*)g_P4;
    const float* R0 = (const float*)g_R0b4;
    int x4 = threadIdx.x, y = blockIdx.x*4 + threadIdx.y, z = blockIdx.y;
    int i4 = (z*HH + y)*W4N + x4;

    St sp = gather(P, z, y, x4);
    St sr = gather(R0, z, y, x4);
    float4 u4 = g_U4[i4], v4 = g_V4[i4], w4 = g_W4[i4];
    float4 inv4 = invof4(((const float4*)sg)[i4]);

    float4 op4, owm4, ou4, ov4, ow4;
#pragma unroll
    for (int k = 0; k < 4; k++) {
        int x = 4*x4 + k;
        NBRS(sp, k, pc, pxm, pxp, pym, pyp, pzm, pzp);
        NBRS(sr, k, rc, rxm, rxp, rym, ryp, rzm, rzp);

        float wm   = wmat(g_W1, z, y, x);
        float p2c  = pc  - wm                    - rc  * INVD;
        float p2xm = pxm - wmat(g_W1, z, y, x-1) - rxm * INVD;
        float p2xp = pxp - wmat(g_W1, z, y, x+1) - rxp * INVD;
        float p2ym = pym - wmat(g_W1, z, y-1, x) - rym * INVD;
        float p2yp = pyp - wmat(g_W1, z, y+1, x) - ryp * INVD;
        float p2zm = pzm - wmat(g_W1, z-1, y, x) - rzm * INVD;
        float p2zp = pzp - wmat(g_W1, z+1, y, x) - rzp * INVD;

        float dxp = 0.5f*(p2xp - p2xm);
        float dyp = 0.5f*(p2yp - p2ym);
        float dzp = 0.5f*(p2zp - p2zm);

        float invc = g(inv4, k);
        setk(op4, k, p2c);
        setk(owm4, k, wm);
        setk(ou4, k, (g(u4,k) - dxp*DT) * invc);
        setk(ov4, k, (g(v4,k) - dyp*DT) * invc);
        setk(ow4, k, (g(w4,k) - dzp*DT) * invc);
    }
    ((float4*)out_p)[i4]   = op4;
    ((float4*)out_wmg)[i4] = owm4;
    ((float4*)ou)[i4] = ou4;
    ((float4*)ov)[i4] = ov4;
    ((float4*)ow)[i4] = ow4;
}

// ---------------- launch ----------------
extern "C" void kernel_launch(void* const* d_in, const int* in_sizes, int n_in,
                              void* d_out, int out_size) {
    const float* vu = (const float*)d_in[0];
    const float* vv = (const float*)d_in[1];
    const float* vw = (const float*)d_in[2];
    const float* vp = (const float*)d_in[3];
    const float* sg = (const float*)d_in[4];

    float* out     = (float*)d_out;
    float* out_u   = out;
    float* out_v   = out + (size_t)NFULL;
    float* out_w   = out + (size_t)2*NFULL;
    float* out_p   = out + (size_t)3*NFULL;
    float* out_wmg = out + (size_t)4*NFULL;
    float* out_r   = out + (size_t)5*NFULL;

    dim3 blk(W4N, 4, 1);          // 192 threads
    dim3 grd(HH/4, DD);           // 4608 blocks
    dim3 grd2(HH/4, DD/2);        // 2304 blocks (fused R1 producers)
    int rblk = (NL3*32 + 255)/256; // 864 blocks, warp per R3 cell

    k_pred  <<<grd, blk>>>(vu, vv, vw, vp, sg);
    k_stage3<<<grd, blk>>>(vu, vv, vw, vp, sg);

    // ---- MG iteration 1 (p = vp): residual + R1 fused ----
    k_residb<<<grd2, blk>>>(vp);
    k_restrict13<<<rblk, 256>>>(nullptr);
    k_smooth2<<<(NL2+255)/256, 256>>>();
    k_smooth1<<<(NL1+255)/256, 256>>>();

    // ---- fused: P = p1; R0b = lap(d) + r0; R1 = restrict(R0b) ----
    k_pup_resid<<<grd2, blk>>>(vp);

    // ---- MG iteration 2 coarse solve ----
    k_restrict13<<<rblk, 256>>>(out_r);
    k_smooth2<<<(NL2+255)/256, 256>>>();
    k_smooth1<<<(NL1+255)/256, 256>>>();

    k_pfinal<<<grd, blk>>>(sg, out_p, out_wmg, out_u, out_v, out_w);
}

// round 17
// speedup vs baseline: 1.0411x; 1.0153x over previous
#include <cuda_runtime.h>

#define DD 96
#define HH 192
#define WW 192
#define W4N (WW/4)                // 48
#define NFULL (DD*HH*WW)          // 3538944
#define NQ    (NFULL/4)
#define NL1 (48*96*96)            // 442368
#define NL2 (24*48*48)            // 55296
#define NL3 (12*24*24)            // 6912

#define DT   0.01f
#define RE   0.001f
#define INVD (-1.0f/6.0f)         // 1/diag, diag = -6

// ---------------- scratch (device globals, float4-aligned) ----------------
__device__ float4 g_U4[NQ], g_V4[NQ], g_W4[NQ];
__device__ float4 g_BU4[NQ], g_BV4[NQ], g_BW4[NQ];
__device__ float4 g_R04[NQ], g_R0b4[NQ], g_P4[NQ];
__device__ float g_R1[NL1], g_R3[NL3];
__device__ float g_W2[NL2], g_W1[NL1];

// ---------------- helpers ----------------
__device__ __forceinline__ float g(const float4 v, int k) {
    switch (k) { case 0: return v.x; case 1: return v.y; case 2: return v.z; default: return v.w; }
}
__device__ __forceinline__ void setk(float4& v, int k, float val) {
    switch (k) { case 0: v.x = val; break; case 1: v.y = val; break;
                 case 2: v.z = val; break; default: v.w = val; }
}

// 1/(1+DT*s) to 1e-8 rel err for DT*s in [0, 0.01): (1-x)(1+x^2); 3 FMA, no MUFU
__device__ __forceinline__ float invof(float s) {
    float x = DT * s;
    return (1.0f - x) * fmaf(x, x, 1.0f);
}
__device__ __forceinline__ float4 invof4(float4 s) {
    return make_float4(invof(s.x), invof(s.y), invof(s.z), invof(s.w));
}

struct St { float4 c, ym, yp, zm, zp; float xm, xp; };

__device__ __forceinline__ St gather(const float* __restrict__ f, int z, int y, int x4) {
    St s;
    const float4* f4 = (const float4*)f;
    s.c  = f4[(z*HH + y)*W4N + x4];
    s.ym = (y > 0)    ? f4[(z*HH + y-1)*W4N + x4]   : make_float4(0,0,0,0);
    s.yp = (y < HH-1) ? f4[(z*HH + y+1)*W4N + x4]   : make_float4(0,0,0,0);
    s.zm = (z > 0)    ? f4[((z-1)*HH + y)*W4N + x4] : make_float4(0,0,0,0);
    s.zp = (z < DD-1) ? f4[((z+1)*HH + y)*W4N + x4] : make_float4(0,0,0,0);
    int base = (z*HH + y)*WW + 4*x4;
    s.xm = (x4 > 0)     ? f[base - 1] : 0.0f;
    s.xp = (x4 < W4N-1) ? f[base + 4] : 0.0f;
    return s;
}

// elementwise invof over a whole stencil (computed ONCE, reused for u,v,w)
__device__ __forceinline__ St inv_st(const St& s) {
    St r;
    r.c  = invof4(s.c);
    r.ym = invof4(s.ym); r.yp = invof4(s.yp);
    r.zm = invof4(s.zm); r.zp = invof4(s.zp);
    r.xm = invof(s.xm);  r.xp = invof(s.xp);
    return r;
}

// pure multiplies
__device__ __forceinline__ void damp(St& a, const St& s) {
    a.c.x*=s.c.x;   a.c.y*=s.c.y;   a.c.z*=s.c.z;   a.c.w*=s.c.w;
    a.ym.x*=s.ym.x; a.ym.y*=s.ym.y; a.ym.z*=s.ym.z; a.ym.w*=s.ym.w;
    a.yp.x*=s.yp.x; a.yp.y*=s.yp.y; a.yp.z*=s.yp.z; a.yp.w*=s.yp.w;
    a.zm.x*=s.zm.x; a.zm.y*=s.zm.y; a.zm.z*=s.zm.z; a.zm.w*=s.zm.w;
    a.zp.x*=s.zp.x; a.zp.y*=s.zp.y; a.zp.z*=s.zp.z; a.zp.w*=s.zp.w;
    a.xm*=s.xm;     a.xp*=s.xp;
}

#define NBRS(sf, k, fc, fxm, fxp, fym, fyp, fzm, fzp)                       \
    float fc  = g((sf).c, k);                                               \
    float fxm = (k)     ? g((sf).c, (k)-1) : (sf).xm;                       \
    float fxp = ((k)<3) ? g((sf).c, (k)+1) : (sf).xp;                       \
    float fym = g((sf).ym, k), fyp = g((sf).yp, k);                         \
    float fzm = g((sf).zm, k), fzp = g((sf).zp, k);

// W1 prolongation fetch (zero outside domain)
__device__ __forceinline__ float wmat(const float* __restrict__ w1, int z, int y, int x) {
    if ((unsigned)z >= (unsigned)DD || (unsigned)y >= (unsigned)HH || (unsigned)x >= (unsigned)WW)
        return 0.0f;
    return w1[((z>>1)*(HH/2) + (y>>1))*(WW/2) + (x>>1)];
}

// ---------------- predictor: BU/BV/BW ----------------
__global__ __launch_bounds__(192) void k_pred(const float* __restrict__ vu,
                                              const float* __restrict__ vv,
                                              const float* __restrict__ vw,
                                              const float* __restrict__ vp,
                                              const float* __restrict__ sg) {
    int x4 = threadIdx.x, y = blockIdx.x*4 + threadIdx.y, z = blockIdx.y;

    St ss = gather(sg, z, y, x4);
    St si = inv_st(ss);
    St su = gather(vu, z, y, x4); damp(su, si);
    St sv = gather(vv, z, y, x4); damp(sv, si);
    St sw = gather(vw, z, y, x4); damp(sw, si);
    St sp = gather(vp, z, y, x4);

    float4 bu4, bv4, bw4;
#pragma unroll
    for (int k = 0; k < 4; k++) {
        int x = 4*x4 + k;
        int nout = (x==0)+(x==WW-1)+(y==0)+(y==HH-1)+(z==0)+(z==DD-1);
        float hn = 0.5f * (float)nout;
        float invc = g(si.c, k);

        NBRS(su, k, uc, uxm, uxp, uym, uyp, uzm, uzp);
        NBRS(sv, k, vc, vxm, vxp, vym, vyp, vzm, vzp);
        NBRS(sw, k, wc, wxm, wxp, wym, wyp, wzm, wzp);
        NBRS(sp, k, pc, pxm, pxp, pym, pyp, pzm, pzp);
        (void)pc;

        float dxp = 0.5f*(pxp-pxm), dyp = 0.5f*(pyp-pym), dzp = 0.5f*(pzp-pzm);

        float ku = (uxm+uxp+uym+uyp+uzm+uzp - 6.0f*uc) + hn*uc;
        float kv = (vxm+vxp+vym+vyp+vzm+vzp - 6.0f*vc) + hn*vc;
        float kw = (wxm+wxp+wym+wyp+wzm+wzp - 6.0f*wc) + hn*wc;

        float dxu = 0.5f*(uxp-uxm), dyu = 0.5f*(uyp-uym), dzu = 0.5f*(uzp-uzm);
        float dxv = 0.5f*(vxp-vxm), dyv = 0.5f*(vyp-vym), dzv = 0.5f*(vzp-vzm);
        float dxw = 0.5f*(wxp-wxm), dyw = 0.5f*(wyp-wym), dzw = 0.5f*(wzp-wzm);

        setk(bu4, k, (uc + 0.5f*(RE*ku*DT - uc*dxu*DT - vc*dyu*DT - wc*dzu*DT) - dxp*DT) * invc);
        setk(bv4, k, (vc + 0.5f*(RE*kv*DT - uc*dxv*DT - vc*dyv*DT - wc*dzv*DT) - dyp*DT) * invc);
        setk(bw4, k, (wc + 0.5f*(RE*kw*DT - uc*dxw*DT - vc*dyw*DT - wc*dzw*DT) - dzp*DT) * invc);
    }
    int i4 = (z*HH + y)*W4N + x4;
    g_BU4[i4] = bu4; g_BV4[i4] = bv4; g_BW4[i4] = bw4;
}

// ---------------- corrector: write U,V,W ----------------
__global__ __launch_bounds__(192) void k_stage3(const float* __restrict__ vu,
                                                const float* __restrict__ vv,
                                                const float* __restrict__ vw,
                                                const float* __restrict__ vp,
                                                const float* __restrict__ sg) {
    const float* BU = (const float*)g_BU4;
    const float* BV = (const float*)g_BV4;
    const float* BW = (const float*)g_BW4;
    int x4 = threadIdx.x, y = blockIdx.x*4 + threadIdx.y, z = blockIdx.y;
    int i4 = (z*HH + y)*W4N + x4;

    St sbu = gather(BU, z, y, x4);
    St sbv = gather(BV, z, y, x4);
    St sbw = gather(BW, z, y, x4);
    St sp  = gather(vp, z, y, x4);

    float4 inv4 = invof4(((const float4*)sg)[i4]);
    float4 u0 = ((const float4*)vu)[i4];
    float4 v0 = ((const float4*)vv)[i4];
    float4 w0 = ((const float4*)vw)[i4];

    float4 un4, vn4, wn4;
#pragma unroll
    for (int k = 0; k < 4; k++) {
        int x = 4*x4 + k;
        int nout = (x==0)+(x==WW-1)+(y==0)+(y==HH-1)+(z==0)+(z==DD-1);
        float hn = 0.5f * (float)nout;
        float invc = g(inv4, k);
        float uc = g(u0,k)*invc, vc = g(v0,k)*invc, wc = g(w0,k)*invc;

        NBRS(sbu, k, buc, buxm, buxp, buym, buyp, buzm, buzp);
        NBRS(sbv, k, bvc, bvxm, bvxp, bvym, bvyp, bvzm, bvzp);
        NBRS(sbw, k, bwc, bwxm, bwxp, bwym, bwyp, bwzm, bwzp);
        NBRS(sp,  k, pc,  pxm,  pxp,  pym,  pyp,  pzm,  pzp);
        (void)pc;

        float dxp = 0.5f*(pxp-pxm), dyp = 0.5f*(pyp-pym), dzp = 0.5f*(pzp-pzm);

        float kub = (buxm+buxp+buym+buyp+buzm+buzp - 6.0f*buc) + hn*buc;
        float kvb = (bvxm+bvxp+bvym+bvyp+bvzm+bvzp - 6.0f*bvc) + hn*bvc;
        float kwb = (bwxm+bwxp+bwym+bwyp+bwzm+bwzp - 6.0f*bwc) + hn*bwc;

        float dx_bu=0.5f*(buxp-buxm), dy_bu=0.5f*(buyp-buym), dz_bu=0.5f*(buzp-buzm);
        float dx_bv=0.5f*(bvxp-bvxm), dy_bv=0.5f*(bvyp-bvym), dz_bv=0.5f*(bvzp-bvzm);
        float dx_bw=0.5f*(bwxp-bwxm), dy_bw=0.5f*(bwyp-bwym), dz_bw=0.5f*(bwzp-bwzm);

        setk(un4, k, (uc + RE*kub*DT - buc*dx_bu*DT - bvc*dy_bu*DT - bwc*dz_bu*DT - dxp*DT) * invc);
        setk(vn4, k, (vc + RE*kvb*DT - buc*dx_bv*DT - bvc*dy_bv*DT - bwc*dz_bv*DT - dyp*DT) * invc);
        setk(wn4, k, (wc + RE*kwb*DT - buc*dx_bw*DT - bvc*dy_bw*DT - bwc*dz_bw*DT - dzp*DT) * invc);
    }
    g_U4[i4] = un4; g_V4[i4] = vn4; g_W4[i4] = wn4;
}

// shared tail: reduce 2x4x192 plane-pair of r values into 192 R1 cells
__device__ __forceinline__ void r1_tail(float4 (&sm)[2][4][48], int by, int bz) {
    __syncthreads();
    int tid = threadIdx.y*48 + threadIdx.x;   // 0..191
    int cx = tid % 96, cy = tid / 96;         // cy 0..1
    const float* s0 = (const float*)&sm[0][2*cy][0];
    const float* s1 = (const float*)&sm[0][2*cy+1][0];
    const float* s2 = (const float*)&sm[1][2*cy][0];
    const float* s3 = (const float*)&sm[1][2*cy+1][0];
    float sum = s0[2*cx] + s0[2*cx+1] + s1[2*cx] + s1[2*cx+1]
              + s2[2*cx] + s2[2*cx+1] + s3[2*cx] + s3[2*cx+1];
    g_R1[(bz*96 + by*2 + cy)*96 + cx] = 0.125f * sum;
}

// ------- fine residual (iter 1) + fused R0->R1 restriction -------
__global__ __launch_bounds__(192) void k_residb(const float* __restrict__ vp) {
    __shared__ float4 sm[2][4][48];
    const float* U = (const float*)g_U4;
    const float* V = (const float*)g_V4;
    const float* W = (const float*)g_W4;
    int x4 = threadIdx.x, ty = threadIdx.y;
    int y = blockIdx.x*4 + ty;
    int z0 = blockIdx.y*2;

#pragma unroll
    for (int zi = 0; zi < 2; zi++) {
        int z = z0 + zi;
        int i4 = (z*HH + y)*W4N + x4;

        float4 ucv = ((const float4*)U)[i4];
        int base = (z*HH + y)*WW + 4*x4;
        float uxm_s = (x4 > 0)     ? U[base - 1] : 0.0f;
        float uxp_s = (x4 < W4N-1) ? U[base + 4] : 0.0f;

        const float4* V4 = (const float4*)V;
        float4 vym = (y > 0)    ? V4[(z*HH + y-1)*W4N + x4] : make_float4(0,0,0,0);
        float4 vyp = (y < HH-1) ? V4[(z*HH + y+1)*W4N + x4] : make_float4(0,0,0,0);

        const float4* Wp4 = (const float4*)W;
        float4 wzm = (z > 0)    ? Wp4[((z-1)*HH + y)*W4N + x4] : make_float4(0,0,0,0);
        float4 wzp = (z < DD-1) ? Wp4[((z+1)*HH + y)*W4N + x4] : make_float4(0,0,0,0);

        St sp = gather(vp, z, y, x4);

        float4 r4;
#pragma unroll
        for (int k = 0; k < 4; k++) {
            float uxm = k ? g(ucv,k-1) : uxm_s;
            float uxp = (k<3) ? g(ucv,k+1) : uxp_s;
            float dxu = 0.5f*(uxp - uxm);
            float dyv = 0.5f*(g(vyp,k) - g(vym,k));
            float dzw = 0.5f*(g(wzp,k) - g(wzm,k));
            float b = -(dxu + dyv + dzw) * (1.0f/DT);

            NBRS(sp, k, pc, pxm, pxp, pym, pyp, pzm, pzp);
            float lap = pxm+pxp+pym+pyp+pzm+pzp - 6.0f*pc;
            setk(r4, k, lap - b);
        }
        g_R04[i4] = r4;
        sm[zi][ty][x4] = r4;
    }
    r1_tail(sm, blockIdx.x, blockIdx.y);
}

// ------- double restriction R1->R3: 2 cells/warp, float4 loads, width-16 shuffles -------
__global__ __launch_bounds__(256) void k_restrict13(float* __restrict__ mirror) {
    int warp = (blockIdx.x*256 + threadIdx.x) >> 5;
    int lane = threadIdx.x & 31;
    int half = lane >> 4;               // 0/1: which cell this half-warp handles
    int l = lane & 15;                  // 0..15 within cell
    int cell = warp*2 + half;
    if (cell >= NL3) return;
    int x3 = cell % 24, t = cell / 24, y3 = t % 24, z3 = t / 24;

    int z1 = 4*z3 + (l >> 2);
    int y1 = 4*y3 + (l & 3);
    float4 a = *(const float4*)(g_R1 + (z1*96 + y1)*96 + 4*x3);
    float s = (a.x + a.y) + (a.z + a.w);
    s += __shfl_down_sync(0xffffffffu, s, 8, 16);
    s += __shfl_down_sync(0xffffffffu, s, 4, 16);
    s += __shfl_down_sync(0xffffffffu, s, 2, 16);
    s += __shfl_down_sync(0xffffffffu, s, 1, 16);
    if (l == 0) {
        float r3 = s * (1.0f/64.0f);
        g_R3[cell] = r3;
        if (mirror) mirror[cell] = r3;
    }
}

// ---- L2 smooth with inline r2 = avg8(R1) ----
__global__ __launch_bounds__(256) void k_smooth2() {
    int i = blockIdx.x*blockDim.x + threadIdx.x;
    if (i >= NL2) return;
    int x = i % 48, t = i / 48, y = t % 48, z = t / 48;
    auto wp = [&](int zz, int yy, int xx) -> float {
        if ((unsigned)zz >= 24u || (unsigned)yy >= 48u || (unsigned)xx >= 48u)
            return 0.0f;
        return INVD * g_R3[((zz>>1)*24 + (yy>>1))*24 + (xx>>1)];
    };
    float c = wp(z,y,x);
    float a = wp(z,y,x-1)+wp(z,y,x+1)+wp(z,y-1,x)+wp(z,y+1,x)+wp(z-1,y,x)+wp(z+1,y,x) - 6.0f*c;

    const float* b = g_R1 + ((2*z)*96 + 2*y)*96 + 2*x;
    float2 a0 = *(const float2*)(b);
    float2 a1 = *(const float2*)(b + 96);
    float2 a2 = *(const float2*)(b + 96*96);
    float2 a3 = *(const float2*)(b + 96*96 + 96);
    float r2 = 0.125f*(a0.x+a0.y + a1.x+a1.y + a2.x+a2.y + a3.x+a3.y);

    g_W2[i] = c - a*INVD + r2*INVD;
}

// ---- L1 smooth, x4-vectorized: W1 = w2p - A0(w2p)/diag + r1/diag ----
__global__ __launch_bounds__(256) void k_smooth1() {
    int i = blockIdx.x*blockDim.x + threadIdx.x;
    if (i >= NL1/4) return;
    int q = i % 24, t = i / 24, y = t % 96, z = t / 96;

    float4 r1 = ((const float4*)g_R1)[(z*96 + y)*24 + q];

    int cz = z >> 1, cy = y >> 1;
    int czm = (z-1) >> 1, czp = (z+1) >> 1, cym = (y-1) >> 1, cyp = (y+1) >> 1;
    bool ym_ok = (y > 0), yp_ok = (y < 95), zm_ok = (z > 0), zp_ok = (z < 47);

    float wc_r[4], wym_r[4], wyp_r[4], wzm_r[4], wzp_r[4];
#pragma unroll
    for (int m = 0; m < 4; m++) {
        int cx = 2*q - 1 + m;
        bool xok = (unsigned)cx < 48u;
        wc_r[m]  = xok          ? g_W2[(cz *48 + cy )*48 + cx] : 0.0f;
        wym_r[m] = (xok && ym_ok) ? g_W2[(cz *48 + cym)*48 + cx] : 0.0f;
        wyp_r[m] = (xok && yp_ok) ? g_W2[(cz *48 + cyp)*48 + cx] : 0.0f;
        wzm_r[m] = (xok && zm_ok) ? g_W2[(czm*48 + cy )*48 + cx] : 0.0f;
        wzp_r[m] = (xok && zp_ok) ? g_W2[(czp*48 + cy )*48 + cx] : 0.0f;
    }

    float4 o;
#pragma unroll
    for (int k = 0; k < 4; k++) {
        int mc  = (k >> 1) + 1;                       // coarse idx of fine x
        int mxm = (k == 0) ? 0 : ((k-1) >> 1) + 1;    // coarse idx of fine x-1
        int mxp = ((k+1) >> 1) + 1;                   // coarse idx of fine x+1
        float c  = wc_r[mc];
        float xm = wc_r[mxm];        // cx<0 already zeroed; x==0 implies cx=-1 -> 0
        float xp = wc_r[mxp];        // x==191 implies cx=48 -> 0
        float a = xm + xp + wym_r[mc] + wyp_r[mc] + wzm_r[mc] + wzp_r[mc] - 6.0f*c;
        setk(o, k, c - a*INVD + g(r1,k)*INVD);
    }
    ((float4*)g_W1)[(z*96 + y)*24 + q] = o;
}

// -------- fused iter-1 p-update + iter-2 residual + R0b->R1 restriction --------
__global__ __launch_bounds__(192) void k_pup_resid(const float* __restrict__ vp) {
    __shared__ float4 sm[2][4][48];
    const float* R0 = (const float*)g_R04;
    int x4 = threadIdx.x, ty = threadIdx.y;
    int y = blockIdx.x*4 + ty;
    int z0 = blockIdx.y*2;

#pragma unroll
    for (int zi = 0; zi < 2; zi++) {
        int z = z0 + zi;
        int i4 = (z*HH + y)*W4N + x4;

        St sr = gather(R0, z, y, x4);
        float4 pc4 = ((const float4*)vp)[i4];

        float4 p4, rr4;
#pragma unroll
        for (int k = 0; k < 4; k++) {
            int x = 4*x4 + k;
            NBRS(sr, k, rc, rxm, rxp, rym, ryp, rzm, rzp);

            float dc  = -wmat(g_W1, z, y, x)   - rc  * INVD;
            float dxm = -wmat(g_W1, z, y, x-1) - rxm * INVD;
            float dxp = -wmat(g_W1, z, y, x+1) - rxp * INVD;
            float dym = -wmat(g_W1, z, y-1, x) - rym * INVD;
            float dyp = -wmat(g_W1, z, y+1, x) - ryp * INVD;
            float dzm = -wmat(g_W1, z-1, y, x) - rzm * INVD;
            float dzp = -wmat(g_W1, z+1, y, x) - rzp * INVD;

            float lapd = dxm + dxp + dym + dyp + dzm + dzp - 6.0f*dc;
            setk(p4, k, g(pc4, k) + dc);
            setk(rr4, k, lapd + rc);
        }
        g_P4[i4] = p4;
        g_R0b4[i4] = rr4;
        sm[zi][ty][x4] = rr4;
    }
    r1_tail(sm, blockIdx.x, blockIdx.y);
}

// -------- fused iter-2 p-update + final projection + sb --------
__global__ __launch_bounds__(192) void k_pfinal(const float* __restrict__ sg,
                                                float* __restrict__ out_p, float* __restrict__ out_wmg,
                                                float* __restrict__ ou, float* __restrict__ ov,
                                                float* __restrict__ ow) {
    const float* P  = (const float*)g_P4;
    const float* R0 = (const float*)g_R0b4;
    int x4 = threadIdx.x, y = blockIdx.x*4 + threadIdx.y, z = blockIdx.y;
    int i4 = (z*HH + y)*W4N + x4;

    St sp = gather(P, z, y, x4);
    St sr = gather(R0, z, y, x4);
    float4 u4 = g_U4[i4], v4 = g_V4[i4], w4 = g_W4[i4];
    float4 inv4 = invof4(((const float4*)sg)[i4]);

    float4 op4, owm4, ou4, ov4, ow4;
#pragma unroll
    for (int k = 0; k < 4; k++) {
        int x = 4*x4 + k;
        NBRS(sp, k, pc, pxm, pxp, pym, pyp, pzm, pzp);
        NBRS(sr, k, rc, rxm, rxp, rym, ryp, rzm, rzp);

        float wm   = wmat(g_W1, z, y, x);
        float p2c  = pc  - wm                    - rc  * INVD;
        float p2xm = pxm - wmat(g_W1, z, y, x-1) - rxm * INVD;
        float p2xp = pxp - wmat(g_W1, z, y, x+1) - rxp * INVD;
        float p2ym = pym - wmat(g_W1, z, y-1, x) - rym * INVD;
        float p2yp = pyp - wmat(g_W1, z, y+1, x) - ryp * INVD;
        float p2zm = pzm - wmat(g_W1, z-1, y, x) - rzm * INVD;
        float p2zp = pzp - wmat(g_W1, z+1, y, x) - rzp * INVD;

        float dxp = 0.5f*(p2xp - p2xm);
        float dyp = 0.5f*(p2yp - p2ym);
        float dzp = 0.5f*(p2zp - p2zm);

        float invc = g(inv4, k);
        setk(op4, k, p2c);
        setk(owm4, k, wm);
        setk(ou4, k, (g(u4,k) - dxp*DT) * invc);
        setk(ov4, k, (g(v4,k) - dyp*DT) * invc);
        setk(ow4, k, (g(w4,k) - dzp*DT) * invc);
    }
    ((float4*)out_p)[i4]   = op4;
    ((float4*)out_wmg)[i4] = owm4;
    ((float4*)ou)[i4] = ou4;
    ((float4*)ov)[i4] = ov4;
    ((float4*)ow)[i4] = ow4;
}

// ---------------- launch ----------------
extern "C" void kernel_launch(void* const* d_in, const int* in_sizes, int n_in,
                              void* d_out, int out_size) {
    const float* vu = (const float*)d_in[0];
    const float* vv = (const float*)d_in[1];
    const float* vw = (const float*)d_in[2];
    const float* vp = (const float*)d_in[3];
    const float* sg = (const float*)d_in[4];

    float* out     = (float*)d_out;
    float* out_u   = out;
    float* out_v   = out + (size_t)NFULL;
    float* out_w   = out + (size_t)2*NFULL;
    float* out_p   = out + (size_t)3*NFULL;
    float* out_wmg = out + (size_t)4*NFULL;
    float* out_r   = out + (size_t)5*NFULL;

    dim3 blk(W4N, 4, 1);          // 192 threads
    dim3 grd(HH/4, DD);           // 4608 blocks
    dim3 grd2(HH/4, DD/2);        // 2304 blocks (fused R1 producers)
    int rblk = (NL3/2*32 + 255)/256;   // 432 blocks: 2 R3 cells per warp
    int s1blk = (NL1/4 + 255)/256;     // 432 blocks: x4-vectorized smooth1

    k_pred  <<<grd, blk>>>(vu, vv, vw, vp, sg);
    k_stage3<<<grd, blk>>>(vu, vv, vw, vp, sg);

    // ---- MG iteration 1 (p = vp): residual + R1 fused ----
    k_residb<<<grd2, blk>>>(vp);
    k_restrict13<<<rblk, 256>>>(nullptr);
    k_smooth2<<<(NL2+255)/256, 256>>>();
    k_smooth1<<<s1blk, 256>>>();

    // ---- fused: P = p1; R0b = lap(d) + r0; R1 = restrict(R0b) ----
    k_pup_resid<<<grd2, blk>>>(vp);

    // ---- MG iteration 2 coarse solve ----
    k_restrict13<<<rblk, 256>>>(out_r);
    k_smooth2<<<(NL2+255)/256, 256>>>();
    k_smooth1<<<s1blk, 256>>>();

    k_pfinal<<<grd, blk>>>(sg, out_p, out_wmg, out_u, out_v, out_w);
}